// round 12
// baseline (speedup 1.0000x reference)
#include <cuda_runtime.h>
#include <cstdint>
#include <cstddef>
#include <math_constants.h>

#define WIN_ 256
typedef unsigned long long u64;

// ---------------- packed f32x2 helpers ----------------
__device__ __forceinline__ u64 bc2(float x) {
    u64 r; asm("mov.b64 %0, {%1, %1};" : "=l"(r) : "f"(x)); return r;
}
__device__ __forceinline__ void fma2(u64& d, u64 a, u64 b) {
    asm("fma.rn.f32x2 %0, %1, %2, %0;" : "+l"(d) : "l"(a), "l"(b));
}
__device__ __forceinline__ void mul2(u64& d, u64 a) {
    asm("mul.rn.f32x2 %0, %0, %1;" : "+l"(d) : "l"(a));
}
__device__ __forceinline__ float2 up2(u64 v) {
    float2 f; asm("mov.b64 {%0, %1}, %2;" : "=f"(f.x), "=f"(f.y) : "l"(v)); return f;
}

// ---------------- device-global scratch ----------------
__device__ float g_q1[(size_t)2 * 16 * 1024 * 128];
__device__ float g_q2[(size_t)2 * 16 * 1024 * 128];
__device__ float g_k1[(size_t)2 * 8 * 1024 * 128];
__device__ float g_k2[(size_t)2 * 8 * 1024 * 128];
__device__ float g_v [(size_t)2 * 8 * 1024 * 128];
__device__ float g_ao[(size_t)2 * 1024 * 2048];

// ============================================================================
// fp32 SGEMM 128x128 tile, BK=16, 256 threads, double-buffered.
// MOV-free FFMA2 core via A-SIDE duplication (broadcast-safe):
//   As[k][2m],As[k][2m+1] = A[m][k];  A LDS.128 = 16-lane broadcast (ty-only).
// Inner k-step: 4 LDS.128(A) + 2 LDS.128(B) + 32 FFMA2 = 38 slots (was 52).
// Acc layout + B path + epilogues identical to the proven R3/R8 kernel.
// Dynamic smem 49.7KB/CTA, 2 CTAs/SM.
// ============================================================================
#define ASTRIDE 260                    // 256 dup floats + 4 pad
#define ASZ     (16 * ASTRIDE)         // floats per A buffer
#define BSZ     (16 * 128)

template<int MODE>
__global__ __launch_bounds__(256, 2)
void gemm_kernel(const float* __restrict__ A,
                 const float* __restrict__ W0,
                 const float* __restrict__ W1,
                 const float* __restrict__ W2,
                 const float* __restrict__ fc,
                 const float* __restrict__ fs,
                 float* __restrict__ outp)
{
    extern __shared__ float smg[];
    float* Asm = smg;                  // [2][16][ASTRIDE]
    float* Bsm = smg + 2 * ASZ;        // [2][16][128]

    const int tid = threadIdx.x;
    const int tx  = tid & 15;
    const int ty  = tid >> 4;
    const int bm  = blockIdx.y * 128;
    const int ct  = blockIdx.x;

    const float* Ap = (MODE == 1) ? g_ao : A;
    const float* Bp;
    int ldb, coff;
    if (MODE == 1)    { Bp = W0; ldb = 2048; coff = ct * 128; }
    else if (ct < 16) { Bp = W0; ldb = 2048; coff = ct * 128; }
    else if (ct < 24) { Bp = W1; ldb = 1024; coff = (ct - 16) * 128; }
    else              { Bp = W2; ldb = 1024; coff = (ct - 24) * 128; }

    const int K  = 2048;
    const int KT = K / 16;

    const int a_row = tid >> 2;        // 0..63 (+64 for p=1)
    const int a_k4  = (tid & 3) << 2;  // k offset 0,4,8,12
    const int b_k   = tid >> 5;
    const int b_c4  = (tid & 31) << 2;

    u64 acc[8][4];                     // identical layout to proven kernel
#pragma unroll
    for (int i = 0; i < 8; ++i)
#pragma unroll
        for (int j = 0; j < 4; ++j) acc[i][j] = 0ull;

    float4 ra[2], rb[2];
#pragma unroll
    for (int p = 0; p < 2; ++p) {
        ra[p] = *(const float4*)&Ap[(size_t)(bm + a_row + p * 64) * K + a_k4];
        rb[p] = *(const float4*)&Bp[(size_t)(b_k + p * 8) * ldb + coff + b_c4];
    }
#pragma unroll
    for (int p = 0; p < 2; ++p) {
        float* ab = Asm + (size_t)0 * ASZ;
        const int m2 = 2 * (a_row + p * 64);
        *(float2*)&ab[(a_k4 + 0) * ASTRIDE + m2] = make_float2(ra[p].x, ra[p].x);
        *(float2*)&ab[(a_k4 + 1) * ASTRIDE + m2] = make_float2(ra[p].y, ra[p].y);
        *(float2*)&ab[(a_k4 + 2) * ASTRIDE + m2] = make_float2(ra[p].z, ra[p].z);
        *(float2*)&ab[(a_k4 + 3) * ASTRIDE + m2] = make_float2(ra[p].w, ra[p].w);
        *(float4*)&Bsm[(size_t)0 * BSZ + (b_k + p * 8) * 128 + b_c4] = rb[p];
    }
    __syncthreads();

    for (int kt = 0; kt < KT; ++kt) {
        const int buf = kt & 1;
        if (kt + 1 < KT) {
            const int ko = (kt + 1) * 16;
#pragma unroll
            for (int p = 0; p < 2; ++p) {
                ra[p] = *(const float4*)&Ap[(size_t)(bm + a_row + p * 64) * K + ko + a_k4];
                rb[p] = *(const float4*)&Bp[(size_t)(ko + b_k + p * 8) * ldb + coff + b_c4];
            }
        }
        const float* ab = Asm + (size_t)buf * ASZ;
        const float* bb = Bsm + (size_t)buf * BSZ;
#pragma unroll
        for (int k = 0; k < 16; ++k) {
            ulonglong2 A0 = *(const ulonglong2*)&ab[k * ASTRIDE + ty * 8];
            ulonglong2 A1 = *(const ulonglong2*)&ab[k * ASTRIDE + ty * 8 + 4];
            ulonglong2 A2 = *(const ulonglong2*)&ab[k * ASTRIDE + 128 + ty * 8];
            ulonglong2 A3 = *(const ulonglong2*)&ab[k * ASTRIDE + 128 + ty * 8 + 4];
            ulonglong2 b0 = *(const ulonglong2*)&bb[k * 128 + tx * 4];
            ulonglong2 b1 = *(const ulonglong2*)&bb[k * 128 + 64 + tx * 4];
            u64 ap[8] = {A0.x, A0.y, A1.x, A1.y, A2.x, A2.y, A3.x, A3.y};
            u64 bv[4] = {b0.x, b0.y, b1.x, b1.y};
#pragma unroll
            for (int i = 0; i < 8; ++i)
#pragma unroll
                for (int j = 0; j < 4; ++j)
                    fma2(acc[i][j], ap[i], bv[j]);
        }
        if (kt + 1 < KT) {
            const int nb = buf ^ 1;
            float* abn = Asm + (size_t)nb * ASZ;
#pragma unroll
            for (int p = 0; p < 2; ++p) {
                const int m2 = 2 * (a_row + p * 64);
                *(float2*)&abn[(a_k4 + 0) * ASTRIDE + m2] = make_float2(ra[p].x, ra[p].x);
                *(float2*)&abn[(a_k4 + 1) * ASTRIDE + m2] = make_float2(ra[p].y, ra[p].y);
                *(float2*)&abn[(a_k4 + 2) * ASTRIDE + m2] = make_float2(ra[p].z, ra[p].z);
                *(float2*)&abn[(a_k4 + 3) * ASTRIDE + m2] = make_float2(ra[p].w, ra[p].w);
                *(float4*)&Bsm[(size_t)nb * BSZ + (b_k + p * 8) * 128 + b_c4] = rb[p];
            }
        }
        __syncthreads();
    }

    if (MODE == 0) {
#pragma unroll
        for (int i = 0; i < 8; ++i) {
            const int ml  = (i < 4) ? (ty * 4 + i) : (64 + ty * 4 + i - 4);
            const int row = bm + ml;
            const int bb  = row >> 10;
            const int ss  = row & 1023;
#pragma unroll
            for (int j2 = 0; j2 < 4; ++j2) {
                const int nl = (j2 < 2) ? (tx * 4 + 2 * j2) : (64 + tx * 4 + 2 * j2 - 4);
                const int t  = nl >> 1;
                float2 xz = up2(acc[i][j2]);
                const float xr = xz.x;
                const float xi = xz.y;
                if (ct < 16) {
                    const int h = ct;
                    const size_t off = ((size_t)(bb * 16 + h) * 1024 + ss) * 128 + nl;
                    const float c1 = fc[ss * 64 + t], s1 = fs[ss * 64 + t];
                    g_q1[off]     = xr * c1 - xi * s1;
                    g_q1[off + 1] = xr * s1 + xi * c1;
                    const float cw = fc[WIN_ * 64 + t], sw = fs[WIN_ * 64 + t];
                    g_q2[off]     = xr * cw - xi * sw;
                    g_q2[off + 1] = xr * sw + xi * cw;
                } else if (ct < 24) {
                    const int h = ct - 16;
                    const size_t off = ((size_t)(bb * 8 + h) * 1024 + ss) * 128 + nl;
                    const float c1 = fc[ss * 64 + t], s1 = fs[ss * 64 + t];
                    g_k1[off]     = xr * c1 - xi * s1;
                    g_k1[off + 1] = xr * s1 + xi * c1;
                    g_k2[off]     = xr;
                    g_k2[off + 1] = xi;
                } else {
                    const int h = ct - 24;
                    const size_t off = ((size_t)(bb * 8 + h) * 1024 + ss) * 128 + nl;
                    g_v[off]     = xr;
                    g_v[off + 1] = xi;
                }
            }
        }
    } else {
#pragma unroll
        for (int i = 0; i < 8; ++i) {
            const int ml = (i < 4) ? (ty * 4 + i) : (64 + ty * 4 + i - 4);
            const size_t row = (size_t)(bm + ml);
            float2 p0 = up2(acc[i][0]), p1 = up2(acc[i][1]);
            float2 p2 = up2(acc[i][2]), p3 = up2(acc[i][3]);
            *(float4*)&outp[row * 2048 + ct * 128 + tx * 4] =
                make_float4(p0.x, p0.y, p1.x, p1.y);
            *(float4*)&outp[row * 2048 + ct * 128 + 64 + tx * 4] =
                make_float4(p2.x, p2.y, p3.x, p3.y);
        }
    }
}

// ============================================================================
// Flash attention — byte-identical to R8 (best: 64x64 tiles, dual-Q,
// register prefetch, 147KB, 1 CTA/SM, 256 threads).
// ============================================================================
__device__ __forceinline__ void load_T64(float* __restrict__ dst,
                                         const float* __restrict__ src)
{
    const int t  = threadIdx.x;
    const int r  = t >> 2;
    const int d0 = (t & 3) * 32;
    const float* s = src + (size_t)r * 128 + d0;
#pragma unroll
    for (int q = 0; q < 8; ++q) {
        float4 v = *(const float4*)(s + q * 4);
        const int d = d0 + q * 4;
        dst[(d + 0) * 64 + r] = v.x;
        dst[(d + 1) * 64 + r] = v.y;
        dst[(d + 2) * 64 + r] = v.z;
        dst[(d + 3) * 64 + r] = v.w;
    }
}

__device__ __forceinline__ void qk_gemm(const float* __restrict__ Qs,
                                        const float* __restrict__ Ks,
                                        int ty, int tx, u64 Sp[4][2])
{
#pragma unroll
    for (int i = 0; i < 4; ++i) { Sp[i][0] = 0ull; Sp[i][1] = 0ull; }
#pragma unroll 4
    for (int d = 0; d < 128; ++d) {
        float4 a = *(const float4*)&Qs[d * 64 + ty * 4];
        ulonglong2 b = *(const ulonglong2*)&Ks[d * 64 + tx * 4];
        float av[4] = {a.x, a.y, a.z, a.w};
#pragma unroll
        for (int i = 0; i < 4; ++i) {
            u64 ai = bc2(av[i]);
            fma2(Sp[i][0], ai, b.x);
            fma2(Sp[i][1], ai, b.y);
        }
    }
}

__global__ __launch_bounds__(256, 1)
void flash_kernel()
{
    extern __shared__ float smf[];
    float* Qa = smf;
    float* Qb = Qa + 8192;
    float* Ks = Qb + 8192;
    float* Vs = Ks + 8192;
    float* Ps = Vs + 8192;

    const int bh = blockIdx.y;
    const int b  = bh >> 4;
    const int h  = bh & 15;
    const int kh = h >> 1;
    const int qt = 15 - (int)blockIdx.x;
    const int i0 = qt * 64;

    const int tid = threadIdx.x;
    const int ty  = tid >> 4;
    const int tx  = tid & 15;
    const float scale = 0.08838834764831845f;

    const int lr  = tid >> 2;
    const int ld0 = (tid & 3) * 32;

    const float* kb1 = g_k1 + ((size_t)(b * 8 + kh) * 1024) * 128;
    const float* kb2 = g_k2 + ((size_t)(b * 8 + kh) * 1024) * 128;
    const float* vb  = g_v  + ((size_t)(b * 8 + kh) * 1024) * 128;

    float4 kreg[8], vreg[8];

#define ZONE_OF(j0) (((j0) >= i0 - 192) ? 0 : (((j0) == i0 - 256) ? 1 : 2))
#define PREFETCH(ktv) do { \
    const int j0p = (ktv) * 64; \
    const float* kb = ((ZONE_OF(j0p) == 2) ? kb2 : kb1) + (size_t)j0p * 128; \
    const float* vp = vb + (size_t)j0p * 128; \
    const float* ks = kb + (size_t)lr * 128 + ld0; \
    const float* vs = vp + (size_t)lr * 128 + ld0; \
    _Pragma("unroll") \
    for (int q = 0; q < 8; ++q) { \
        kreg[q] = *(const float4*)(ks + q * 4); \
        vreg[q] = *(const float4*)(vs + q * 4); \
    } } while (0)

    PREFETCH(0);
    load_T64(Qa, g_q1 + ((size_t)(b * 16 + h) * 1024 + i0) * 128);
    load_T64(Qb, g_q2 + ((size_t)(b * 16 + h) * 1024 + i0) * 128);

    u64 Op[4][4];
    float mo[4], l[4];
#pragma unroll
    for (int i = 0; i < 4; ++i) {
        mo[i] = -CUDART_INF_F;
        l[i]  = 0.f;
#pragma unroll
        for (int c = 0; c < 4; ++c) Op[i][c] = 0ull;
    }

    for (int kt = 0; kt <= qt; ++kt) {
        const int j0 = kt * 64;
        const int zone = ZONE_OF(j0);

#pragma unroll
        for (int q = 0; q < 8; ++q) {
            const int d = ld0 + q * 4;
            Ks[(d + 0) * 64 + lr] = kreg[q].x;
            Ks[(d + 1) * 64 + lr] = kreg[q].y;
            Ks[(d + 2) * 64 + lr] = kreg[q].z;
            Ks[(d + 3) * 64 + lr] = kreg[q].w;
            *(float4*)&Vs[lr * 128 + d] = vreg[q];
        }
        if (kt < qt) PREFETCH(kt + 1);
        __syncthreads();

        u64 SpA[4][2];
        qk_gemm((zone == 2) ? Qb : Qa, Ks, ty, tx, SpA);

        float val[4][4];
        if (zone == 1) {
            __syncthreads();
            load_T64(Ks, kb2 + (size_t)j0 * 128);
            __syncthreads();
            u64 SpB[4][2];
            qk_gemm(Qb, Ks, ty, tx, SpB);
#pragma unroll
            for (int i = 0; i < 4; ++i) {
                const int ig = i0 + ty * 4 + i;
                float2 a0 = up2(SpA[i][0]), a1 = up2(SpA[i][1]);
                float2 b0 = up2(SpB[i][0]), b1 = up2(SpB[i][1]);
                float sa[4]  = {a0.x, a0.y, a1.x, a1.y};
                float sbv[4] = {b0.x, b0.y, b1.x, b1.y};
#pragma unroll
                for (int j = 0; j < 4; ++j) {
                    const int jg = j0 + tx * 4 + j;
                    val[i][j] = ((jg > ig - WIN_) ? sa[j] : sbv[j]) * scale;
                }
            }
        } else {
            const bool diag = (j0 == i0);
#pragma unroll
            for (int i = 0; i < 4; ++i) {
                const int ig = i0 + ty * 4 + i;
                float2 a0 = up2(SpA[i][0]), a1 = up2(SpA[i][1]);
                float sa[4] = {a0.x, a0.y, a1.x, a1.y};
#pragma unroll
                for (int j = 0; j < 4; ++j) {
                    const int jg = j0 + tx * 4 + j;
                    float v = sa[j] * scale;
                    if (diag && jg > ig) v = -CUDART_INF_F;
                    val[i][j] = v;
                }
            }
        }

        float mr[4], al[4];
#pragma unroll
        for (int i = 0; i < 4; ++i) {
            float m = val[i][0];
            m = fmaxf(m, val[i][1]);
            m = fmaxf(m, val[i][2]);
            m = fmaxf(m, val[i][3]);
#pragma unroll
            for (int off = 8; off >= 1; off >>= 1)
                m = fmaxf(m, __shfl_xor_sync(0xffffffffu, m, off));
            m = fmaxf(m, mo[i]);
            al[i] = __expf(mo[i] - m);
            mo[i] = m;
            float s = 0.f;
#pragma unroll
            for (int j = 0; j < 4; ++j) {
                float p = __expf(val[i][j] - m);
                val[i][j] = p;
                s += p;
            }
            mr[i] = s;
        }
#pragma unroll
        for (int i = 0; i < 4; ++i) {
            float s = mr[i];
#pragma unroll
            for (int off = 8; off >= 1; off >>= 1)
                s += __shfl_xor_sync(0xffffffffu, s, off);
            l[i] = l[i] * al[i] + s;
            u64 av = bc2(al[i]);
#pragma unroll
            for (int c = 0; c < 4; ++c) mul2(Op[i][c], av);
            *(float4*)&Ps[(ty * 4 + i) * 64 + tx * 4] =
                make_float4(val[i][0], val[i][1], val[i][2], val[i][3]);
        }
        __syncthreads();

#pragma unroll 2
        for (int j = 0; j < 64; ++j) {
            ulonglong2 v0 = *(const ulonglong2*)&Vs[j * 128 + tx * 4];
            ulonglong2 v1 = *(const ulonglong2*)&Vs[j * 128 + 64 + tx * 4];
            u64 vv[4] = {v0.x, v0.y, v1.x, v1.y};
#pragma unroll
            for (int i = 0; i < 4; ++i) {
                u64 pi = bc2(Ps[(ty * 4 + i) * 64 + j]);
#pragma unroll
                for (int c = 0; c < 4; ++c)
                    fma2(Op[i][c], pi, vv[c]);
            }
        }
        __syncthreads();
    }

#pragma unroll
    for (int i = 0; i < 4; ++i) {
        const float inv = 1.f / l[i];
        u64 iv = bc2(inv);
#pragma unroll
        for (int c = 0; c < 4; ++c) mul2(Op[i][c], iv);
        const int ig = i0 + ty * 4 + i;
        float* dst = g_ao + ((size_t)(b * 1024 + ig)) * 2048 + h * 128;
        float2 p0 = up2(Op[i][0]), p1 = up2(Op[i][1]);
        float2 p2 = up2(Op[i][2]), p3 = up2(Op[i][3]);
        *(float4*)&dst[tx * 4]      = make_float4(p0.x, p0.y, p1.x, p1.y);
        *(float4*)&dst[64 + tx * 4] = make_float4(p2.x, p2.y, p3.x, p3.y);
    }
#undef PREFETCH
#undef ZONE_OF
}

// ============================================================================
extern "C" void kernel_launch(void* const* d_in, const int* in_sizes, int n_in,
                              void* d_out, int out_size)
{
    const float* x  = (const float*)d_in[0];
    const float* fc = (const float*)d_in[1];
    const float* fs = (const float*)d_in[2];
    const float* wq = (const float*)d_in[3];
    const float* wk = (const float*)d_in[4];
    const float* wv = (const float*)d_in[5];
    const float* wo = (const float*)d_in[6];
    float* out = (float*)d_out;

    const int G_SMEM = (2 * ASZ + 2 * BSZ) * 4;   // 49664 bytes
    cudaFuncSetAttribute(gemm_kernel<0>,
                         cudaFuncAttributeMaxDynamicSharedMemorySize, G_SMEM);
    cudaFuncSetAttribute(gemm_kernel<1>,
                         cudaFuncAttributeMaxDynamicSharedMemorySize, G_SMEM);
    cudaFuncSetAttribute(flash_kernel,
                         cudaFuncAttributeMaxDynamicSharedMemorySize, 147456);

    gemm_kernel<0><<<dim3(32, 16), 256, G_SMEM>>>(x, wq, wk, wv, fc, fs, nullptr);
    flash_kernel<<<dim3(16, 32), 256, 147456>>>();
    gemm_kernel<1><<<dim3(16, 16), 256, G_SMEM>>>(nullptr, wo, nullptr, nullptr,
                                                  nullptr, nullptr, out);
}

// round 13
// speedup vs baseline: 1.1807x; 1.1807x over previous
#include <cuda_runtime.h>
#include <cstdint>
#include <cstddef>
#include <math_constants.h>

#define WIN_ 256
typedef unsigned long long u64;

// ---------------- packed f32x2 helpers ----------------
__device__ __forceinline__ u64 bc2(float x) {
    u64 r; asm("mov.b64 %0, {%1, %1};" : "=l"(r) : "f"(x)); return r;
}
__device__ __forceinline__ void fma2(u64& d, u64 a, u64 b) {
    asm("fma.rn.f32x2 %0, %1, %2, %0;" : "+l"(d) : "l"(a), "l"(b));
}
__device__ __forceinline__ void mul2(u64& d, u64 a) {
    asm("mul.rn.f32x2 %0, %0, %1;" : "+l"(d) : "l"(a));
}
__device__ __forceinline__ float2 up2(u64 v) {
    float2 f; asm("mov.b64 {%0, %1}, %2;" : "=f"(f.x), "=f"(f.y) : "l"(v)); return f;
}

// ---------------- device-global scratch ----------------
__device__ float g_q1[(size_t)2 * 16 * 1024 * 128];
__device__ float g_q2[(size_t)2 * 16 * 1024 * 128];
__device__ float g_k1[(size_t)2 * 8 * 1024 * 128];
__device__ float g_k2[(size_t)2 * 8 * 1024 * 128];
__device__ float g_v [(size_t)2 * 8 * 1024 * 128];
__device__ float g_ao[(size_t)2 * 1024 * 2048];

// ============================================================================
// fp32 SGEMM 128x128 tile, BK=16, 256 threads, double-buffered, FFMA2 core.
// (Proven R3/R8 kernel, byte-identical — 699us control. DO NOT TOUCH.)
// ============================================================================
template<int MODE>
__global__ __launch_bounds__(256, 2)
void gemm_kernel(const float* __restrict__ A,
                 const float* __restrict__ W0,
                 const float* __restrict__ W1,
                 const float* __restrict__ W2,
                 const float* __restrict__ fc,
                 const float* __restrict__ fs,
                 float* __restrict__ outp)
{
    __shared__ float As[2][16][132];
    __shared__ float Bs[2][16][128];

    const int tid = threadIdx.x;
    const int tx  = tid & 15;
    const int ty  = tid >> 4;
    const int bm  = blockIdx.y * 128;
    const int ct  = blockIdx.x;

    const float* Ap = (MODE == 1) ? g_ao : A;
    const float* Bp;
    int ldb, coff;
    if (MODE == 1)    { Bp = W0; ldb = 2048; coff = ct * 128; }
    else if (ct < 16) { Bp = W0; ldb = 2048; coff = ct * 128; }
    else if (ct < 24) { Bp = W1; ldb = 1024; coff = (ct - 16) * 128; }
    else              { Bp = W2; ldb = 1024; coff = (ct - 24) * 128; }

    const int K  = 2048;
    const int KT = K / 16;

    const int a_row = tid >> 2;
    const int a_k4  = (tid & 3) << 2;
    const int b_k   = tid >> 5;
    const int b_c4  = (tid & 31) << 2;

    u64 acc[8][4];
#pragma unroll
    for (int i = 0; i < 8; ++i)
#pragma unroll
        for (int j = 0; j < 4; ++j) acc[i][j] = 0ull;

    float4 ra[2], rb[2];
#pragma unroll
    for (int p = 0; p < 2; ++p) {
        ra[p] = *(const float4*)&Ap[(size_t)(bm + a_row + p * 64) * K + a_k4];
        rb[p] = *(const float4*)&Bp[(size_t)(b_k + p * 8) * ldb + coff + b_c4];
    }
#pragma unroll
    for (int p = 0; p < 2; ++p) {
        As[0][a_k4 + 0][a_row + p * 64] = ra[p].x;
        As[0][a_k4 + 1][a_row + p * 64] = ra[p].y;
        As[0][a_k4 + 2][a_row + p * 64] = ra[p].z;
        As[0][a_k4 + 3][a_row + p * 64] = ra[p].w;
        *(float4*)&Bs[0][b_k + p * 8][b_c4] = rb[p];
    }
    __syncthreads();

    for (int kt = 0; kt < KT; ++kt) {
        const int buf = kt & 1;
        if (kt + 1 < KT) {
            const int ko = (kt + 1) * 16;
#pragma unroll
            for (int p = 0; p < 2; ++p) {
                ra[p] = *(const float4*)&Ap[(size_t)(bm + a_row + p * 64) * K + ko + a_k4];
                rb[p] = *(const float4*)&Bp[(size_t)(ko + b_k + p * 8) * ldb + coff + b_c4];
            }
        }
#pragma unroll
        for (int k = 0; k < 16; ++k) {
            float4 a0 = *(const float4*)&As[buf][k][ty * 4];
            float4 a1 = *(const float4*)&As[buf][k][64 + ty * 4];
            ulonglong2 b0 = *(const ulonglong2*)&Bs[buf][k][tx * 4];
            ulonglong2 b1 = *(const ulonglong2*)&Bs[buf][k][64 + tx * 4];
            u64 bv[4] = {b0.x, b0.y, b1.x, b1.y};
            float av[8] = {a0.x, a0.y, a0.z, a0.w, a1.x, a1.y, a1.z, a1.w};
#pragma unroll
            for (int i = 0; i < 8; ++i) {
                u64 ai = bc2(av[i]);
#pragma unroll
                for (int j = 0; j < 4; ++j)
                    fma2(acc[i][j], ai, bv[j]);
            }
        }
        if (kt + 1 < KT) {
            const int nb = buf ^ 1;
#pragma unroll
            for (int p = 0; p < 2; ++p) {
                As[nb][a_k4 + 0][a_row + p * 64] = ra[p].x;
                As[nb][a_k4 + 1][a_row + p * 64] = ra[p].y;
                As[nb][a_k4 + 2][a_row + p * 64] = ra[p].z;
                As[nb][a_k4 + 3][a_row + p * 64] = ra[p].w;
                *(float4*)&Bs[nb][b_k + p * 8][b_c4] = rb[p];
            }
        }
        __syncthreads();
    }

    if (MODE == 0) {
#pragma unroll
        for (int i = 0; i < 8; ++i) {
            const int ml  = (i < 4) ? (ty * 4 + i) : (64 + ty * 4 + i - 4);
            const int row = bm + ml;
            const int bb  = row >> 10;
            const int ss  = row & 1023;
#pragma unroll
            for (int j2 = 0; j2 < 4; ++j2) {
                const int nl = (j2 < 2) ? (tx * 4 + 2 * j2) : (64 + tx * 4 + 2 * j2 - 4);
                const int t  = nl >> 1;
                float2 xz = up2(acc[i][j2]);
                const float xr = xz.x;
                const float xi = xz.y;
                if (ct < 16) {
                    const int h = ct;
                    const size_t off = ((size_t)(bb * 16 + h) * 1024 + ss) * 128 + nl;
                    const float c1 = fc[ss * 64 + t], s1 = fs[ss * 64 + t];
                    g_q1[off]     = xr * c1 - xi * s1;
                    g_q1[off + 1] = xr * s1 + xi * c1;
                    const float cw = fc[WIN_ * 64 + t], sw = fs[WIN_ * 64 + t];
                    g_q2[off]     = xr * cw - xi * sw;
                    g_q2[off + 1] = xr * sw + xi * cw;
                } else if (ct < 24) {
                    const int h = ct - 16;
                    const size_t off = ((size_t)(bb * 8 + h) * 1024 + ss) * 128 + nl;
                    const float c1 = fc[ss * 64 + t], s1 = fs[ss * 64 + t];
                    g_k1[off]     = xr * c1 - xi * s1;
                    g_k1[off + 1] = xr * s1 + xi * c1;
                    g_k2[off]     = xr;
                    g_k2[off + 1] = xi;
                } else {
                    const int h = ct - 24;
                    const size_t off = ((size_t)(bb * 8 + h) * 1024 + ss) * 128 + nl;
                    g_v[off]     = xr;
                    g_v[off + 1] = xi;
                }
            }
        }
    } else {
#pragma unroll
        for (int i = 0; i < 8; ++i) {
            const int ml = (i < 4) ? (ty * 4 + i) : (64 + ty * 4 + i - 4);
            const size_t row = (size_t)(bm + ml);
            float2 p0 = up2(acc[i][0]), p1 = up2(acc[i][1]);
            float2 p2 = up2(acc[i][2]), p3 = up2(acc[i][3]);
            *(float4*)&outp[row * 2048 + ct * 128 + tx * 4] =
                make_float4(p0.x, p0.y, p1.x, p1.y);
            *(float4*)&outp[row * 2048 + ct * 128 + 64 + tx * 4] =
                make_float4(p2.x, p2.y, p3.x, p3.y);
        }
    }
}

// ============================================================================
// Flash attention v5: R8 math/traffic, barrier surgery.
//  - K/V double-buffered (208KB smem): tail sync removed (WAR closed by the
//    single block sync, proof in header comment).
//  - Ps producer==consumer warp -> middle sync is __syncwarp().
//  - 1 block sync per tile (zone-1 rare path keeps local syncs).
// ============================================================================
__device__ __forceinline__ void load_T64(float* __restrict__ dst,
                                         const float* __restrict__ src)
{
    const int t  = threadIdx.x;
    const int r  = t >> 2;
    const int d0 = (t & 3) * 32;
    const float* s = src + (size_t)r * 128 + d0;
#pragma unroll
    for (int q = 0; q < 8; ++q) {
        float4 v = *(const float4*)(s + q * 4);
        const int d = d0 + q * 4;
        dst[(d + 0) * 64 + r] = v.x;
        dst[(d + 1) * 64 + r] = v.y;
        dst[(d + 2) * 64 + r] = v.z;
        dst[(d + 3) * 64 + r] = v.w;
    }
}

__device__ __forceinline__ void qk_gemm(const float* __restrict__ Qs,
                                        const float* __restrict__ Ks,
                                        int ty, int tx, u64 Sp[4][2])
{
#pragma unroll
    for (int i = 0; i < 4; ++i) { Sp[i][0] = 0ull; Sp[i][1] = 0ull; }
#pragma unroll 4
    for (int d = 0; d < 128; ++d) {
        float4 a = *(const float4*)&Qs[d * 64 + ty * 4];
        ulonglong2 b = *(const ulonglong2*)&Ks[d * 64 + tx * 4];
        float av[4] = {a.x, a.y, a.z, a.w};
#pragma unroll
        for (int i = 0; i < 4; ++i) {
            u64 ai = bc2(av[i]);
            fma2(Sp[i][0], ai, b.x);
            fma2(Sp[i][1], ai, b.y);
        }
    }
}

__global__ __launch_bounds__(256, 1)
void flash_kernel()
{
    extern __shared__ float smf[];
    float* Qa  = smf;                 //  8192
    float* Qb  = smf + 8192;          //  8192
    float* Ksb = smf + 16384;         //  2 x 8192  [buf][d][r]
    float* Vsb = smf + 32768;         //  2 x 8192  [buf][r][d]
    float* Ps  = smf + 49152;         //  4096      -> 53248 fl = 212992 B

    const int bh = blockIdx.y;
    const int b  = bh >> 4;
    const int h  = bh & 15;
    const int kh = h >> 1;
    const int qt = 15 - (int)blockIdx.x;
    const int i0 = qt * 64;

    const int tid = threadIdx.x;
    const int ty  = tid >> 4;
    const int tx  = tid & 15;
    const float scale = 0.08838834764831845f;

    const int lr  = tid >> 2;
    const int ld0 = (tid & 3) * 32;

    const float* kb1 = g_k1 + ((size_t)(b * 8 + kh) * 1024) * 128;
    const float* kb2 = g_k2 + ((size_t)(b * 8 + kh) * 1024) * 128;
    const float* vb  = g_v  + ((size_t)(b * 8 + kh) * 1024) * 128;

    float4 kreg[8], vreg[8];

#define ZONE_OF(j0) (((j0) >= i0 - 192) ? 0 : (((j0) == i0 - 256) ? 1 : 2))
#define PREFETCH(ktv) do { \
    const int j0p = (ktv) * 64; \
    const float* kb = ((ZONE_OF(j0p) == 2) ? kb2 : kb1) + (size_t)j0p * 128; \
    const float* vp = vb + (size_t)j0p * 128; \
    const float* ks = kb + (size_t)lr * 128 + ld0; \
    const float* vs = vp + (size_t)lr * 128 + ld0; \
    _Pragma("unroll") \
    for (int q = 0; q < 8; ++q) { \
        kreg[q] = *(const float4*)(ks + q * 4); \
        vreg[q] = *(const float4*)(vs + q * 4); \
    } } while (0)

    PREFETCH(0);
    load_T64(Qa, g_q1 + ((size_t)(b * 16 + h) * 1024 + i0) * 128);
    load_T64(Qb, g_q2 + ((size_t)(b * 16 + h) * 1024 + i0) * 128);

    u64 Op[4][4];
    float mo[4], l[4];
#pragma unroll
    for (int i = 0; i < 4; ++i) {
        mo[i] = -CUDART_INF_F;
        l[i]  = 0.f;
#pragma unroll
        for (int c = 0; c < 4; ++c) Op[i][c] = 0ull;
    }

    for (int kt = 0; kt <= qt; ++kt) {
        const int j0   = kt * 64;
        const int zone = ZONE_OF(j0);
        const int buf  = kt & 1;
        float* Ks = Ksb + buf * 8192;
        float* Vs = Vsb + buf * 8192;

        // store prefetched K (transposed) and V (row-major) into this buffer
#pragma unroll
        for (int q = 0; q < 8; ++q) {
            const int d = ld0 + q * 4;
            Ks[(d + 0) * 64 + lr] = kreg[q].x;
            Ks[(d + 1) * 64 + lr] = kreg[q].y;
            Ks[(d + 2) * 64 + lr] = kreg[q].z;
            Ks[(d + 3) * 64 + lr] = kreg[q].w;
            *(float4*)&Vs[lr * 128 + d] = vreg[q];
        }
        if (kt < qt) PREFETCH(kt + 1);
        __syncthreads();                 // the ONE block sync per tile

        u64 SpA[4][2];
        qk_gemm((zone == 2) ? Qb : Qa, Ks, ty, tx, SpA);

        float val[4][4];
        if (zone == 1) {
            // rare path (<=1 tile/CTA): k2 into the OTHER buffer w/ local syncs
            float* Kalt = Ksb + (buf ^ 1) * 8192;
            __syncthreads();
            load_T64(Kalt, kb2 + (size_t)j0 * 128);
            __syncthreads();
            u64 SpB[4][2];
            qk_gemm(Qb, Kalt, ty, tx, SpB);
            __syncthreads();             // close race with kt+1's STS into buf^1
#pragma unroll
            for (int i = 0; i < 4; ++i) {
                const int ig = i0 + ty * 4 + i;
                float2 a0 = up2(SpA[i][0]), a1 = up2(SpA[i][1]);
                float2 b0 = up2(SpB[i][0]), b1 = up2(SpB[i][1]);
                float sa[4]  = {a0.x, a0.y, a1.x, a1.y};
                float sbv[4] = {b0.x, b0.y, b1.x, b1.y};
#pragma unroll
                for (int j = 0; j < 4; ++j) {
                    const int jg = j0 + tx * 4 + j;
                    val[i][j] = ((jg > ig - WIN_) ? sa[j] : sbv[j]) * scale;
                }
            }
        } else {
            const bool diag = (j0 == i0);
#pragma unroll
            for (int i = 0; i < 4; ++i) {
                const int ig = i0 + ty * 4 + i;
                float2 a0 = up2(SpA[i][0]), a1 = up2(SpA[i][1]);
                float sa[4] = {a0.x, a0.y, a1.x, a1.y};
#pragma unroll
                for (int j = 0; j < 4; ++j) {
                    const int jg = j0 + tx * 4 + j;
                    float v = sa[j] * scale;
                    if (diag && jg > ig) v = -CUDART_INF_F;
                    val[i][j] = v;
                }
            }
        }

        // --- online softmax (identical math) ---
        float mr[4], al[4];
#pragma unroll
        for (int i = 0; i < 4; ++i) {
            float m = val[i][0];
            m = fmaxf(m, val[i][1]);
            m = fmaxf(m, val[i][2]);
            m = fmaxf(m, val[i][3]);
#pragma unroll
            for (int off = 8; off >= 1; off >>= 1)
                m = fmaxf(m, __shfl_xor_sync(0xffffffffu, m, off));
            m = fmaxf(m, mo[i]);
            al[i] = __expf(mo[i] - m);
            mo[i] = m;
            float s = 0.f;
#pragma unroll
            for (int j = 0; j < 4; ++j) {
                float p = __expf(val[i][j] - m);
                val[i][j] = p;
                s += p;
            }
            mr[i] = s;
        }
#pragma unroll
        for (int i = 0; i < 4; ++i) {
            float s = mr[i];
#pragma unroll
            for (int off = 8; off >= 1; off >>= 1)
                s += __shfl_xor_sync(0xffffffffu, s, off);
            l[i] = l[i] * al[i] + s;
            u64 av = bc2(al[i]);
#pragma unroll
            for (int c = 0; c < 4; ++c) mul2(Op[i][c], av);
            *(float4*)&Ps[(ty * 4 + i) * 64 + tx * 4] =
                make_float4(val[i][0], val[i][1], val[i][2], val[i][3]);
        }
        __syncwarp();   // Ps producer == consumer warp (same ty half-warp)

        // --- P @ V ---
#pragma unroll 2
        for (int j = 0; j < 64; ++j) {
            ulonglong2 v0 = *(const ulonglong2*)&Vs[j * 128 + tx * 4];
            ulonglong2 v1 = *(const ulonglong2*)&Vs[j * 128 + 64 + tx * 4];
            u64 vv[4] = {v0.x, v0.y, v1.x, v1.y};
#pragma unroll
            for (int i = 0; i < 4; ++i) {
                u64 pi = bc2(Ps[(ty * 4 + i) * 64 + j]);
#pragma unroll
                for (int c = 0; c < 4; ++c)
                    fma2(Op[i][c], pi, vv[c]);
            }
        }
        // no tail sync: next STS targets buf^1; its last readers finished
        // before the block sync above (PV(kt-1) < STS(kt) < sync(kt)).
    }

    // epilogue
#pragma unroll
    for (int i = 0; i < 4; ++i) {
        const float inv = 1.f / l[i];
        u64 iv = bc2(inv);
#pragma unroll
        for (int c = 0; c < 4; ++c) mul2(Op[i][c], iv);
        const int ig = i0 + ty * 4 + i;
        float* dst = g_ao + ((size_t)(b * 1024 + ig)) * 2048 + h * 128;
        float2 p0 = up2(Op[i][0]), p1 = up2(Op[i][1]);
        float2 p2 = up2(Op[i][2]), p3 = up2(Op[i][3]);
        *(float4*)&dst[tx * 4]      = make_float4(p0.x, p0.y, p1.x, p1.y);
        *(float4*)&dst[64 + tx * 4] = make_float4(p2.x, p2.y, p3.x, p3.y);
    }
#undef PREFETCH
#undef ZONE_OF
}

// ============================================================================
extern "C" void kernel_launch(void* const* d_in, const int* in_sizes, int n_in,
                              void* d_out, int out_size)
{
    const float* x  = (const float*)d_in[0];
    const float* fc = (const float*)d_in[1];
    const float* fs = (const float*)d_in[2];
    const float* wq = (const float*)d_in[3];
    const float* wk = (const float*)d_in[4];
    const float* wv = (const float*)d_in[5];
    const float* wo = (const float*)d_in[6];
    float* out = (float*)d_out;

    cudaFuncSetAttribute(flash_kernel,
                         cudaFuncAttributeMaxDynamicSharedMemorySize, 212992);

    gemm_kernel<0><<<dim3(32, 16), 256>>>(x, wq, wk, wv, fc, fs, nullptr);
    flash_kernel<<<dim3(16, 32), 256, 212992>>>();
    gemm_kernel<1><<<dim3(16, 16), 256>>>(nullptr, wo, nullptr, nullptr,
                                          nullptr, nullptr, out);
}